// round 15
// baseline (speedup 1.0000x reference)
#include <cuda_runtime.h>
#include <cuda_fp16.h>
#include <cstdint>
#include <math.h>

#define Bq 2
#define Sq 2048
#define Dq 1024
#define Hq 16
#define HDq 64
#define Fq 4096
#define NTOK (Bq*Sq)   // 4096

// ---- scratch (allocation-free) ----
__device__ __half g_h  [NTOK*Dq];
__device__ __half g_q  [NTOK*Dq];
__device__ __half g_k  [NTOK*Dq];
__device__ __half g_v  [NTOK*Dq];
__device__ __half g_att[NTOK*Dq];
__device__ float  g_x2 [NTOK*Dq];
__device__ __half g_h2 [NTOK*Dq];
__device__ __half g_mlp[NTOK*Fq];
// fp16 weights
__device__ __half g_wq[Dq*Dq];
__device__ __half g_wk[Dq*Dq];
__device__ __half g_wv[Dq*Dq];
__device__ __half g_wo[Dq*Dq];
__device__ __half g_w1[Fq*Dq];
__device__ __half g_w2[Dq*Fq];

__device__ __forceinline__ uint32_t smem_u32(const void* p) {
    uint32_t a;
    asm("{ .reg .u64 t; cvta.to.shared.u64 t, %1; cvt.u32.u64 %0, t; }" : "=r"(a) : "l"(p));
    return a;
}
__device__ __forceinline__ void cp_async16(uint32_t dst, const void* src) {
    asm volatile("cp.async.ca.shared.global [%0], [%1], 16;" :: "r"(dst), "l"(src));
}
__device__ __forceinline__ void cp_commit() {
    asm volatile("cp.async.commit_group;" ::: "memory");
}
template <int N>
__device__ __forceinline__ void cp_wait() {
    asm volatile("cp.async.wait_group %0;" :: "n"(N) : "memory");
}
__device__ __forceinline__ void ldsm4(uint32_t* r, uint32_t addr) {
    asm volatile("ldmatrix.sync.aligned.m8n8.x4.shared.b16 {%0,%1,%2,%3}, [%4];"
        : "=r"(r[0]), "=r"(r[1]), "=r"(r[2]), "=r"(r[3]) : "r"(addr));
}
__device__ __forceinline__ void ldsm4t(uint32_t* r, uint32_t addr) {
    asm volatile("ldmatrix.sync.aligned.m8n8.x4.trans.shared.b16 {%0,%1,%2,%3}, [%4];"
        : "=r"(r[0]), "=r"(r[1]), "=r"(r[2]), "=r"(r[3]) : "r"(addr));
}
// fp16 m16n8k16, f32 accumulate
__device__ __forceinline__ void mma_f16(float* c, const uint32_t* a, const uint32_t* b) {
    asm volatile(
        "mma.sync.aligned.m16n8k16.row.col.f32.f16.f16.f32 "
        "{%0,%1,%2,%3}, {%4,%5,%6,%7}, {%8,%9}, {%0,%1,%2,%3};"
        : "+f"(c[0]), "+f"(c[1]), "+f"(c[2]), "+f"(c[3])
        : "r"(a[0]), "r"(a[1]), "r"(a[2]), "r"(a[3]),
          "r"(b[0]), "r"(b[1]));
}

// ================= weight fp16 convert =================
__global__ void wcvt_kernel(const float* __restrict__ wq, const float* __restrict__ wk,
                            const float* __restrict__ wv, const float* __restrict__ wo,
                            const float* __restrict__ w1, const float* __restrict__ w2,
                            __half* oq, __half* ok, __half* ov, __half* oo,
                            __half* o1, __half* o2) {
    const int Qk = Dq * Dq / 4;
    int i4 = blockIdx.x * 256 + threadIdx.x;
    const float* s;
    __half* d;
    int off;
    if (i4 < Qk)            { s = wq; d = oq; off = i4; }
    else if (i4 < 2 * Qk)   { s = wk; d = ok; off = i4 - Qk; }
    else if (i4 < 3 * Qk)   { s = wv; d = ov; off = i4 - 2 * Qk; }
    else if (i4 < 4 * Qk)   { s = wo; d = oo; off = i4 - 3 * Qk; }
    else if (i4 < 8 * Qk)   { s = w1; d = o1; off = i4 - 4 * Qk; }
    else                    { s = w2; d = o2; off = i4 - 8 * Qk; }
    float4 v = ((const float4*)s)[off];
    __half2 lo = __floats2half2_rn(v.x, v.y);
    __half2 hi = __floats2half2_rn(v.z, v.w);
    __half2* dp = (__half2*)(d + (size_t)off * 4);
    dp[0] = lo; dp[1] = hi;
}

// ================= LayerNorm: warp-per-row, no block barriers =============
// 256 threads = 8 warps = 8 rows per CTA; grid = NTOK/8.
// Each lane holds 8 float4 (32 elems); reductions are pure shfl.
__global__ void __launch_bounds__(256)
ln_kernel(const float* __restrict__ x,
          const float* __restrict__ g,
          const float* __restrict__ b,
          __half* __restrict__ out) {
    const int lane = threadIdx.x & 31, wid = threadIdx.x >> 5;
    const int row = blockIdx.x * 8 + wid;
    const float* xr = x + (size_t)row * Dq;
    __half* outr = out + (size_t)row * Dq;

    float4 v[8];
    float sum = 0.f;
#pragma unroll
    for (int i = 0; i < 8; i++) {
        v[i] = *(const float4*)(xr + lane * 4 + i * 128);
        sum += v[i].x + v[i].y + v[i].z + v[i].w;
    }
#pragma unroll
    for (int o = 16; o > 0; o >>= 1) sum += __shfl_xor_sync(0xffffffffu, sum, o);
    const float mu = sum * (1.0f / Dq);

    float vs = 0.f;
#pragma unroll
    for (int i = 0; i < 8; i++) {
        float d0 = v[i].x - mu, d1 = v[i].y - mu, d2 = v[i].z - mu, d3 = v[i].w - mu;
        vs += d0 * d0 + d1 * d1 + d2 * d2 + d3 * d3;
    }
#pragma unroll
    for (int o = 16; o > 0; o >>= 1) vs += __shfl_xor_sync(0xffffffffu, vs, o);
    const float rstd = rsqrtf(vs * (1.0f / Dq) + 1e-5f);

#pragma unroll
    for (int i = 0; i < 8; i++) {
        int c = lane * 4 + i * 128;
        float4 gg = *(const float4*)(g + c);
        float4 bb = *(const float4*)(b + c);
        __half2* op = (__half2*)(outr + c);
        op[0] = __floats2half2_rn((v[i].x - mu) * rstd * gg.x + bb.x,
                                  (v[i].y - mu) * rstd * gg.y + bb.y);
        op[1] = __floats2half2_rn((v[i].z - mu) * rstd * gg.z + bb.z,
                                  (v[i].w - mu) * rstd * gg.w + bb.w);
    }
}

// ================= fp16 mma.sync GEMM body (2-stage, K-chunk 64) ==========
// EPI: 0 = bias -> half; 1 = bias+gelu -> half; 2 = bias + residual -> float
#define HSTR 72
#define STAGE_HALVES (2 * 128 * HSTR)       // 18432 halves
#define STAGE_BYTES  (STAGE_HALVES * 2)     // 36864 B
#define GEMM_SMEM    (2 * STAGE_BYTES)      // 73728 B

template <int EPI>
__device__ __forceinline__ void gemm_body(
    const __half* __restrict__ A, const __half* __restrict__ W,
    const float* __restrict__ bias, const float* __restrict__ res,
    void* __restrict__ Cv, int N, int K, int bm, int bn) {
    extern __shared__ __half smem[];
    const uint32_t smb = smem_u32(smem);
    const int tid = threadIdx.x;
    const int wid = tid >> 5, lane = tid & 31;
    const int warp_m = wid >> 2, warp_n = wid & 3;
    const int g = lane >> 2, t = lane & 3;

    float acc[4][4][4];
#pragma unroll
    for (int i = 0; i < 4; i++)
#pragma unroll
        for (int j = 0; j < 4; j++)
#pragma unroll
            for (int u = 0; u < 4; u++) acc[i][j][u] = 0.f;

    uint32_t dA[4], dW[4];
    const __half* srcA[4];
    const __half* srcW[4];
#pragma unroll
    for (int j = 0; j < 4; j++) {
        int id = tid + j * 256;
        int row = id >> 3, seg = id & 7;
        dA[j] = smb + (uint32_t)(row * 144 + seg * 16);
        dW[j] = dA[j] + (uint32_t)(128 * 144);
        srcA[j] = A + (size_t)(bm + row) * K + seg * 8;
        srcW[j] = W + (size_t)(bn + row) * K + seg * 8;
    }

    const uint32_t aLd = smb + (uint32_t)((warp_m * 64 + (lane & 15)) * 144 + (lane >> 4) * 16);
    const uint32_t bLd = smb + (uint32_t)(128 * 144 + (warp_n * 32 + (lane & 15)) * 144 + (lane >> 4) * 16);
    const int nk = K >> 6;

#pragma unroll
    for (int s = 0; s < 2; s++) {
        uint32_t so = (uint32_t)(s * STAGE_BYTES);
#pragma unroll
        for (int j = 0; j < 4; j++) {
            cp_async16(dA[j] + so, srcA[j] + s * 64);
            cp_async16(dW[j] + so, srcW[j] + s * 64);
        }
        cp_commit();
    }

    for (int kt = 0; kt < nk; kt++) {
        cp_wait<1>();
        __syncthreads();
        const uint32_t so = (uint32_t)((kt & 1) * STAGE_BYTES);
#pragma unroll
        for (int ks = 0; ks < 4; ks++) {
            uint32_t af[4][4];
#pragma unroll
            for (int mt = 0; mt < 4; mt++)
                ldsm4(af[mt], aLd + so + (uint32_t)(mt * (16 * 144) + ks * 32));
            uint32_t bq4[2][4];
#pragma unroll
            for (int pr = 0; pr < 2; pr++)
                ldsm4(bq4[pr], bLd + so + (uint32_t)(pr * (16 * 144) + ks * 32));
#pragma unroll
            for (int mt = 0; mt < 4; mt++) {
#pragma unroll
                for (int nt = 0; nt < 4; nt++) {
                    uint32_t bb[2];
                    bb[0] = bq4[nt >> 1][nt & 1];
                    bb[1] = bq4[nt >> 1][2 + (nt & 1)];
                    mma_f16(acc[mt][nt], af[mt], bb);
                }
            }
        }
        __syncthreads();
        if (kt + 2 < nk) {
            uint32_t so2 = (uint32_t)((kt & 1) * STAGE_BYTES);
            const int koff = (kt + 2) * 64;
#pragma unroll
            for (int j = 0; j < 4; j++) {
                cp_async16(dA[j] + so2, srcA[j] + koff);
                cp_async16(dW[j] + so2, srcW[j] + koff);
            }
        }
        cp_commit();
    }

#pragma unroll
    for (int mt = 0; mt < 4; mt++) {
#pragma unroll
        for (int nt = 0; nt < 4; nt++) {
            int row = bm + warp_m * 64 + mt * 16 + g;
            int col = bn + warp_n * 32 + nt * 8 + 2 * t;
#pragma unroll
            for (int half_i = 0; half_i < 2; half_i++) {
                int r = row + half_i * 8;
                float v0 = acc[mt][nt][half_i * 2 + 0] + bias[col];
                float v1 = acc[mt][nt][half_i * 2 + 1] + bias[col + 1];
                if (EPI == 0) {
                    *(__half2*)((__half*)Cv + (size_t)r * N + col) = __floats2half2_rn(v0, v1);
                } else if (EPI == 1) {
                    float z0 = 0.7978845608028654f * (v0 + 0.044715f * v0 * v0 * v0);
                    float z1 = 0.7978845608028654f * (v1 + 0.044715f * v1 * v1 * v1);
                    v0 = v0 / (1.f + __expf(-2.f * z0));
                    v1 = v1 / (1.f + __expf(-2.f * z1));
                    *(__half2*)((__half*)Cv + (size_t)r * N + col) = __floats2half2_rn(v0, v1);
                } else {
                    v0 += res[(size_t)r * N + col];
                    v1 += res[(size_t)r * N + col + 1];
                    float2 o; o.x = v0; o.y = v1;
                    *(float2*)((float*)Cv + (size_t)r * N + col) = o;
                }
            }
        }
    }
}

template <int EPI>
__global__ void __launch_bounds__(256, 2)
gemm_mma(const __half* __restrict__ A, const __half* __restrict__ W,
         const float* __restrict__ bias, const float* __restrict__ res,
         void* __restrict__ Cv, int M, int N, int K) {
    gemm_body<EPI>(A, W, bias, res, Cv, N, K, blockIdx.y * 128, blockIdx.x * 128);
}

// fused QKV: grid.x = 24 (matrix = x>>3, n-tile = x&7)
__global__ void __launch_bounds__(256, 2)
qkv_mma(const __half* __restrict__ h,
        const __half* __restrict__ wq, const __half* __restrict__ wk, const __half* __restrict__ wv,
        const float* __restrict__ bq, const float* __restrict__ bk, const float* __restrict__ bv,
        __half* __restrict__ q, __half* __restrict__ k, __half* __restrict__ v) {
    int sel = blockIdx.x >> 3;
    int bn = (blockIdx.x & 7) * 128;
    const __half* W = (sel == 0) ? wq : (sel == 1) ? wk : wv;
    const float* bias = (sel == 0) ? bq : (sel == 1) ? bk : bv;
    __half* C = (sel == 0) ? q : (sel == 1) ? k : v;
    gemm_body<0>(h, W, bias, nullptr, C, Dq, Dq, blockIdx.y * 128, bn);
}

// ================= fp16 mma flash attention (R13/R14-proven) ==============
#define AKSTR 72
#define ATT_SH (2 * 64 * AKSTR)
#define ATT_SMEM (2 * ATT_SH * 2)

__global__ void __launch_bounds__(256, 2)
attn_mma(const __half* __restrict__ q, const __half* __restrict__ k,
         const __half* __restrict__ v, __half* __restrict__ out) {
    extern __shared__ __half sm[];
    const uint32_t smb = smem_u32(sm);
    const int tid = threadIdx.x, wid = tid >> 5, lane = tid & 31;
    const int g = lane >> 2, t = lane & 3;
    const int bh = blockIdx.x, b = bh >> 4, h = bh & 15;
    const int q0 = blockIdx.y * 128 + wid * 16;

    const int sr = tid >> 2;
    const int sseg = (tid & 3) * 8;
    const __half* kb0 = k + ((size_t)b * Sq) * Dq + h * HDq;
    const __half* vb0 = v + ((size_t)b * Sq) * Dq + h * HDq;
    const uint32_t dK = smb + (uint32_t)((sr * AKSTR + sseg) * 2);
    const uint32_t dV = dK + (uint32_t)(64 * AKSTR * 2);

    uint32_t aq[4][4];
    {
        const __half* qb = q + ((size_t)(b * Sq + q0)) * Dq + h * HDq;
        const __half2 sc = __floats2half2_rn(0.125f, 0.125f);
#pragma unroll
        for (int ks = 0; ks < 4; ks++) {
            __half2 x0 = __hmul2(*(const __half2*)(qb + (size_t)g * Dq + ks * 16 + 2 * t), sc);
            __half2 x1 = __hmul2(*(const __half2*)(qb + (size_t)(g + 8) * Dq + ks * 16 + 2 * t), sc);
            __half2 x2 = __hmul2(*(const __half2*)(qb + (size_t)g * Dq + ks * 16 + 2 * t + 8), sc);
            __half2 x3 = __hmul2(*(const __half2*)(qb + (size_t)(g + 8) * Dq + ks * 16 + 2 * t + 8), sc);
            aq[ks][0] = *(uint32_t*)&x0;
            aq[ks][1] = *(uint32_t*)&x1;
            aq[ks][2] = *(uint32_t*)&x2;
            aq[ks][3] = *(uint32_t*)&x3;
        }
    }
    const uint32_t kLd = smb + (uint32_t)((((lane & 15)) * AKSTR + 8 * (lane >> 4)) * 2);
    const uint32_t vLd = kLd + (uint32_t)(64 * AKSTR * 2);

    float o[8][4];
#pragma unroll
    for (int nt = 0; nt < 8; nt++)
#pragma unroll
        for (int u = 0; u < 4; u++) o[nt][u] = 0.f;
    float m0 = -1e30f, m1 = -1e30f, l0 = 0.f, l1 = 0.f;

    const int NT = Sq / 64;
    cp_async16(dK,       kb0 + (size_t)sr * Dq + sseg);
    cp_async16(dK + 64u, kb0 + (size_t)sr * Dq + sseg + 32);
    cp_async16(dV,       vb0 + (size_t)sr * Dq + sseg);
    cp_async16(dV + 64u, vb0 + (size_t)sr * Dq + sseg + 32);
    cp_commit();

    for (int kt = 0; kt < NT; kt++) {
        cp_wait<0>();
        __syncthreads();
        if (kt + 1 < NT) {
            uint32_t so = (uint32_t)(((kt + 1) & 1) * ATT_SH * 2);
            const __half* kb = kb0 + (size_t)(kt + 1) * 64 * Dq;
            const __half* vb = vb0 + (size_t)(kt + 1) * 64 * Dq;
            cp_async16(dK + so,       kb + (size_t)sr * Dq + sseg);
            cp_async16(dK + so + 64u, kb + (size_t)sr * Dq + sseg + 32);
            cp_async16(dV + so,       vb + (size_t)sr * Dq + sseg);
            cp_async16(dV + so + 64u, vb + (size_t)sr * Dq + sseg + 32);
            cp_commit();
        }
        const uint32_t so = (uint32_t)((kt & 1) * ATT_SH * 2);

#pragma unroll
        for (int sub = 0; sub < 2; sub++) {
            float s[4][4];
#pragma unroll
            for (int nt = 0; nt < 4; nt++)
#pragma unroll
                for (int u = 0; u < 4; u++) s[nt][u] = 0.f;
#pragma unroll
            for (int ks = 0; ks < 4; ks++) {
#pragma unroll
                for (int pr = 0; pr < 2; pr++) {
                    uint32_t kq[4];
                    ldsm4(kq, kLd + so + (uint32_t)((((sub * 32 + pr * 16) * AKSTR) + ks * 16) * 2));
#pragma unroll
                    for (int half_n = 0; half_n < 2; half_n++) {
                        uint32_t bb[2];
                        bb[0] = kq[half_n];
                        bb[1] = kq[2 + half_n];
                        mma_f16(s[pr * 2 + half_n], aq[ks], bb);
                    }
                }
            }
            float mx0 = fmaxf(fmaxf(s[0][0], s[0][1]), fmaxf(s[1][0], s[1][1]));
            mx0 = fmaxf(mx0, fmaxf(fmaxf(s[2][0], s[2][1]), fmaxf(s[3][0], s[3][1])));
            float mx1 = fmaxf(fmaxf(s[0][2], s[0][3]), fmaxf(s[1][2], s[1][3]));
            mx1 = fmaxf(mx1, fmaxf(fmaxf(s[2][2], s[2][3]), fmaxf(s[3][2], s[3][3])));
            mx0 = fmaxf(mx0, __shfl_xor_sync(0xffffffffu, mx0, 1));
            mx0 = fmaxf(mx0, __shfl_xor_sync(0xffffffffu, mx0, 2));
            mx1 = fmaxf(mx1, __shfl_xor_sync(0xffffffffu, mx1, 1));
            mx1 = fmaxf(mx1, __shfl_xor_sync(0xffffffffu, mx1, 2));
            float nm0 = fmaxf(m0, mx0), nm1 = fmaxf(m1, mx1);
            float c0 = __expf(m0 - nm0), c1 = __expf(m1 - nm1);
            float sum0 = 0.f, sum1 = 0.f;
#pragma unroll
            for (int nt = 0; nt < 4; nt++) {
                s[nt][0] = __expf(s[nt][0] - nm0);
                s[nt][1] = __expf(s[nt][1] - nm0);
                s[nt][2] = __expf(s[nt][2] - nm1);
                s[nt][3] = __expf(s[nt][3] - nm1);
                sum0 += s[nt][0] + s[nt][1];
                sum1 += s[nt][2] + s[nt][3];
            }
            sum0 += __shfl_xor_sync(0xffffffffu, sum0, 1);
            sum0 += __shfl_xor_sync(0xffffffffu, sum0, 2);
            sum1 += __shfl_xor_sync(0xffffffffu, sum1, 1);
            sum1 += __shfl_xor_sync(0xffffffffu, sum1, 2);
            l0 = l0 * c0 + sum0;
            l1 = l1 * c1 + sum1;
#pragma unroll
            for (int nt = 0; nt < 8; nt++) {
                o[nt][0] *= c0; o[nt][1] *= c0;
                o[nt][2] *= c1; o[nt][3] *= c1;
            }
            m0 = nm0; m1 = nm1;

            uint32_t ap[2][4];
#pragma unroll
            for (int j = 0; j < 2; j++) {
                __half2 p0 = __floats2half2_rn(s[2 * j][0], s[2 * j][1]);
                __half2 p1 = __floats2half2_rn(s[2 * j][2], s[2 * j][3]);
                __half2 p2 = __floats2half2_rn(s[2 * j + 1][0], s[2 * j + 1][1]);
                __half2 p3 = __floats2half2_rn(s[2 * j + 1][2], s[2 * j + 1][3]);
                ap[j][0] = *(uint32_t*)&p0;
                ap[j][1] = *(uint32_t*)&p1;
                ap[j][2] = *(uint32_t*)&p2;
                ap[j][3] = *(uint32_t*)&p3;
            }
#pragma unroll
            for (int j = 0; j < 2; j++) {
#pragma unroll
                for (int np = 0; np < 4; np++) {
                    uint32_t vq[4];
                    ldsm4t(vq, vLd + so + (uint32_t)((((sub * 32 + j * 16) * AKSTR) + np * 16) * 2));
#pragma unroll
                    for (int half_n = 0; half_n < 2; half_n++) {
                        uint32_t bb[2];
                        bb[0] = vq[half_n * 2];
                        bb[1] = vq[half_n * 2 + 1];
                        mma_f16(o[np * 2 + half_n], ap[j], bb);
                    }
                }
            }
        }
        __syncthreads();
    }

    float i0 = 1.f / l0, i1 = 1.f / l1;
    __half* ob = out + ((size_t)(b * Sq + q0)) * Dq + h * HDq;
#pragma unroll
    for (int nt = 0; nt < 8; nt++) {
        *(__half2*)(ob + (size_t)g * Dq + nt * 8 + 2 * t) =
            __floats2half2_rn(o[nt][0] * i0, o[nt][1] * i0);
        *(__half2*)(ob + (size_t)(g + 8) * Dq + nt * 8 + 2 * t) =
            __floats2half2_rn(o[nt][2] * i1, o[nt][3] * i1);
    }
}

// ================= launch =================
extern "C" void kernel_launch(void* const* d_in, const int* in_sizes, int n_in,
                              void* d_out, int out_size) {
    const float* x     = (const float*)d_in[0];
    const float* Wq    = (const float*)d_in[1];
    const float* bq    = (const float*)d_in[2];
    const float* Wk    = (const float*)d_in[3];
    const float* bk    = (const float*)d_in[4];
    const float* Wv    = (const float*)d_in[5];
    const float* bv    = (const float*)d_in[6];
    const float* Wo    = (const float*)d_in[7];
    const float* bo    = (const float*)d_in[8];
    const float* ln1_g = (const float*)d_in[9];
    const float* ln1_b = (const float*)d_in[10];
    const float* W1    = (const float*)d_in[11];
    const float* b1    = (const float*)d_in[12];
    const float* W2    = (const float*)d_in[13];
    const float* b2    = (const float*)d_in[14];
    const float* ln2_g = (const float*)d_in[15];
    const float* ln2_b = (const float*)d_in[16];
    float* out = (float*)d_out;

    __half *h, *q, *k, *v, *att, *h2, *mlp, *wq, *wk, *wv, *wo, *w1, *w2;
    float *x2;
    cudaGetSymbolAddress((void**)&h,   g_h);
    cudaGetSymbolAddress((void**)&q,   g_q);
    cudaGetSymbolAddress((void**)&k,   g_k);
    cudaGetSymbolAddress((void**)&v,   g_v);
    cudaGetSymbolAddress((void**)&att, g_att);
    cudaGetSymbolAddress((void**)&x2,  g_x2);
    cudaGetSymbolAddress((void**)&h2,  g_h2);
    cudaGetSymbolAddress((void**)&mlp, g_mlp);
    cudaGetSymbolAddress((void**)&wq,  g_wq);
    cudaGetSymbolAddress((void**)&wk,  g_wk);
    cudaGetSymbolAddress((void**)&wv,  g_wv);
    cudaGetSymbolAddress((void**)&wo,  g_wo);
    cudaGetSymbolAddress((void**)&w1,  g_w1);
    cudaGetSymbolAddress((void**)&w2,  g_w2);

    cudaFuncSetAttribute(gemm_mma<1>, cudaFuncAttributeMaxDynamicSharedMemorySize, GEMM_SMEM);
    cudaFuncSetAttribute(gemm_mma<2>, cudaFuncAttributeMaxDynamicSharedMemorySize, GEMM_SMEM);
    cudaFuncSetAttribute(qkv_mma, cudaFuncAttributeMaxDynamicSharedMemorySize, GEMM_SMEM);
    cudaFuncSetAttribute(attn_mma, cudaFuncAttributeMaxDynamicSharedMemorySize, ATT_SMEM);

    // 0) convert weights to fp16
    const int WTOT4 = (4 * Dq * Dq + 2 * Fq * Dq) / 4;
    wcvt_kernel<<<WTOT4 / 256, 256>>>(Wq, Wk, Wv, Wo, W1, W2, wq, wk, wv, wo, w1, w2);

    // 1) LN1 -> h (half), warp-per-row
    ln_kernel<<<NTOK / 8, 256>>>(x, ln1_g, ln1_b, h);

    // 2) fused QKV -> half
    dim3 gq(24, NTOK / 128);
    qkv_mma<<<gq, 256, GEMM_SMEM>>>(h, wq, wk, wv, bq, bk, bv, q, k, v);

    // 3) attention (fp16 mma) -> att (half)
    dim3 gattn(Bq * Hq, Sq / 128);
    attn_mma<<<gattn, 256, ATT_SMEM>>>(q, k, v, att);

    // 4) output projection + residual -> x2
    dim3 go(Dq / 128, NTOK / 128);
    gemm_mma<2><<<go, 256, GEMM_SMEM>>>(att, wo, bo, x, x2, NTOK, Dq, Dq);

    // 5) LN2 -> h2 (half)
    ln_kernel<<<NTOK / 8, 256>>>(x2, ln2_g, ln2_b, h2);

    // 6) MLP up + gelu -> mlp (half)
    dim3 g1(Fq / 128, NTOK / 128);
    gemm_mma<1><<<g1, 256, GEMM_SMEM>>>(h2, w1, b1, nullptr, mlp, NTOK, Fq, Dq);

    // 7) MLP down + residual -> out
    dim3 g2(Dq / 128, NTOK / 128);
    gemm_mma<2><<<g2, 256, GEMM_SMEM>>>(mlp, w2, b2, x2, out, NTOK, Dq, Fq);
}

// round 16
// speedup vs baseline: 1.5124x; 1.5124x over previous
#include <cuda_runtime.h>
#include <cuda_fp16.h>
#include <cstdint>
#include <math.h>

#define Bq 2
#define Sq 2048
#define Dq 1024
#define Hq 16
#define HDq 64
#define Fq 4096
#define NTOK (Bq*Sq)   // 4096

// ---- scratch (allocation-free) ----
__device__ __half g_h  [NTOK*Dq];
__device__ __half g_q  [NTOK*Dq];
__device__ __half g_k  [NTOK*Dq];
__device__ __half g_v  [NTOK*Dq];
__device__ __half g_att[NTOK*Dq];
__device__ float  g_x2 [NTOK*Dq];
__device__ __half g_h2 [NTOK*Dq];
__device__ __half g_mlp[NTOK*Fq];
// fp16 weights
__device__ __half g_wq[Dq*Dq];
__device__ __half g_wk[Dq*Dq];
__device__ __half g_wv[Dq*Dq];
__device__ __half g_wo[Dq*Dq];
__device__ __half g_w1[Fq*Dq];
__device__ __half g_w2[Dq*Fq];

__device__ __forceinline__ uint32_t smem_u32(const void* p) {
    uint32_t a;
    asm("{ .reg .u64 t; cvta.to.shared.u64 t, %1; cvt.u32.u64 %0, t; }" : "=r"(a) : "l"(p));
    return a;
}
__device__ __forceinline__ void cp_async16(uint32_t dst, const void* src) {
    asm volatile("cp.async.ca.shared.global [%0], [%1], 16;" :: "r"(dst), "l"(src));
}
__device__ __forceinline__ void cp_commit() {
    asm volatile("cp.async.commit_group;" ::: "memory");
}
template <int N>
__device__ __forceinline__ void cp_wait() {
    asm volatile("cp.async.wait_group %0;" :: "n"(N) : "memory");
}
__device__ __forceinline__ void ldsm4(uint32_t* r, uint32_t addr) {
    asm volatile("ldmatrix.sync.aligned.m8n8.x4.shared.b16 {%0,%1,%2,%3}, [%4];"
        : "=r"(r[0]), "=r"(r[1]), "=r"(r[2]), "=r"(r[3]) : "r"(addr));
}
__device__ __forceinline__ void ldsm4t(uint32_t* r, uint32_t addr) {
    asm volatile("ldmatrix.sync.aligned.m8n8.x4.trans.shared.b16 {%0,%1,%2,%3}, [%4];"
        : "=r"(r[0]), "=r"(r[1]), "=r"(r[2]), "=r"(r[3]) : "r"(addr));
}
// fp16 m16n8k16, f32 accumulate
__device__ __forceinline__ void mma_f16(float* c, const uint32_t* a, const uint32_t* b) {
    asm volatile(
        "mma.sync.aligned.m16n8k16.row.col.f32.f16.f16.f32 "
        "{%0,%1,%2,%3}, {%4,%5,%6,%7}, {%8,%9}, {%0,%1,%2,%3};"
        : "+f"(c[0]), "+f"(c[1]), "+f"(c[2]), "+f"(c[3])
        : "r"(a[0]), "r"(a[1]), "r"(a[2]), "r"(a[3]),
          "r"(b[0]), "r"(b[1]));
}

// ================= weight fp16 convert =================
__global__ void wcvt_kernel(const float* __restrict__ wq, const float* __restrict__ wk,
                            const float* __restrict__ wv, const float* __restrict__ wo,
                            const float* __restrict__ w1, const float* __restrict__ w2,
                            __half* oq, __half* ok, __half* ov, __half* oo,
                            __half* o1, __half* o2) {
    const int Qk = Dq * Dq / 4;
    int i4 = blockIdx.x * 256 + threadIdx.x;
    const float* s;
    __half* d;
    int off;
    if (i4 < Qk)            { s = wq; d = oq; off = i4; }
    else if (i4 < 2 * Qk)   { s = wk; d = ok; off = i4 - Qk; }
    else if (i4 < 3 * Qk)   { s = wv; d = ov; off = i4 - 2 * Qk; }
    else if (i4 < 4 * Qk)   { s = wo; d = oo; off = i4 - 3 * Qk; }
    else if (i4 < 8 * Qk)   { s = w1; d = o1; off = i4 - 4 * Qk; }
    else                    { s = w2; d = o2; off = i4 - 8 * Qk; }
    float4 v = ((const float4*)s)[off];
    __half2 lo = __floats2half2_rn(v.x, v.y);
    __half2 hi = __floats2half2_rn(v.z, v.w);
    __half2* dp = (__half2*)(d + (size_t)off * 4);
    dp[0] = lo; dp[1] = hi;
}

// ================= LayerNorm: warp-per-row, no block barriers =============
__global__ void __launch_bounds__(256)
ln_kernel(const float* __restrict__ x,
          const float* __restrict__ g,
          const float* __restrict__ b,
          __half* __restrict__ out) {
    const int lane = threadIdx.x & 31, wid = threadIdx.x >> 5;
    const int row = blockIdx.x * 8 + wid;
    const float* xr = x + (size_t)row * Dq;
    __half* outr = out + (size_t)row * Dq;

    float4 v[8];
    float sum = 0.f;
#pragma unroll
    for (int i = 0; i < 8; i++) {
        v[i] = *(const float4*)(xr + lane * 4 + i * 128);
        sum += v[i].x + v[i].y + v[i].z + v[i].w;
    }
#pragma unroll
    for (int o = 16; o > 0; o >>= 1) sum += __shfl_xor_sync(0xffffffffu, sum, o);
    const float mu = sum * (1.0f / Dq);

    float vs = 0.f;
#pragma unroll
    for (int i = 0; i < 8; i++) {
        float d0 = v[i].x - mu, d1 = v[i].y - mu, d2 = v[i].z - mu, d3 = v[i].w - mu;
        vs += d0 * d0 + d1 * d1 + d2 * d2 + d3 * d3;
    }
#pragma unroll
    for (int o = 16; o > 0; o >>= 1) vs += __shfl_xor_sync(0xffffffffu, vs, o);
    const float rstd = rsqrtf(vs * (1.0f / Dq) + 1e-5f);

#pragma unroll
    for (int i = 0; i < 8; i++) {
        int c = lane * 4 + i * 128;
        float4 gg = *(const float4*)(g + c);
        float4 bb = *(const float4*)(b + c);
        __half2* op = (__half2*)(outr + c);
        op[0] = __floats2half2_rn((v[i].x - mu) * rstd * gg.x + bb.x,
                                  (v[i].y - mu) * rstd * gg.y + bb.y);
        op[1] = __floats2half2_rn((v[i].z - mu) * rstd * gg.z + bb.z,
                                  (v[i].w - mu) * rstd * gg.w + bb.w);
    }
}

// ================= fp16 mma.sync GEMM (2-stage, K-chunk 64) — R14 exact ===
#define HSTR 72
#define STAGE_HALVES (2 * 128 * HSTR)       // 18432 halves
#define STAGE_BYTES  (STAGE_HALVES * 2)     // 36864 B
#define GEMM_SMEM    (2 * STAGE_BYTES)      // 73728 B

template <int EPI>
__global__ void __launch_bounds__(256, 2)
gemm_mma(const __half* __restrict__ A, const __half* __restrict__ W,
         const float* __restrict__ bias, const float* __restrict__ res,
         void* __restrict__ Cv, int M, int N, int K) {
    extern __shared__ __half smem[];
    const uint32_t smb = smem_u32(smem);
    const int tid = threadIdx.x;
    const int wid = tid >> 5, lane = tid & 31;
    const int warp_m = wid >> 2, warp_n = wid & 3;
    const int g = lane >> 2, t = lane & 3;
    const int bm = blockIdx.y * 128, bn = blockIdx.x * 128;

    float acc[4][4][4];
#pragma unroll
    for (int i = 0; i < 4; i++)
#pragma unroll
        for (int j = 0; j < 4; j++)
#pragma unroll
            for (int u = 0; u < 4; u++) acc[i][j][u] = 0.f;

    uint32_t dA[4], dW[4];
    const __half* srcA[4];
    const __half* srcW[4];
#pragma unroll
    for (int j = 0; j < 4; j++) {
        int id = tid + j * 256;
        int row = id >> 3, seg = id & 7;
        dA[j] = smb + (uint32_t)(row * 144 + seg * 16);
        dW[j] = dA[j] + (uint32_t)(128 * 144);
        srcA[j] = A + (size_t)(bm + row) * K + seg * 8;
        srcW[j] = W + (size_t)(bn + row) * K + seg * 8;
    }

    const uint32_t aLd = smb + (uint32_t)((warp_m * 64 + (lane & 15)) * 144 + (lane >> 4) * 16);
    const uint32_t bLd = smb + (uint32_t)(128 * 144 + (warp_n * 32 + (lane & 15)) * 144 + (lane >> 4) * 16);
    const int nk = K >> 6;

#pragma unroll
    for (int s = 0; s < 2; s++) {
        uint32_t so = (uint32_t)(s * STAGE_BYTES);
#pragma unroll
        for (int j = 0; j < 4; j++) {
            cp_async16(dA[j] + so, srcA[j] + s * 64);
            cp_async16(dW[j] + so, srcW[j] + s * 64);
        }
        cp_commit();
    }

    for (int kt = 0; kt < nk; kt++) {
        cp_wait<1>();
        __syncthreads();
        const uint32_t so = (uint32_t)((kt & 1) * STAGE_BYTES);
#pragma unroll
        for (int ks = 0; ks < 4; ks++) {
            uint32_t af[4][4];
#pragma unroll
            for (int mt = 0; mt < 4; mt++)
                ldsm4(af[mt], aLd + so + (uint32_t)(mt * (16 * 144) + ks * 32));
            uint32_t bq4[2][4];
#pragma unroll
            for (int pr = 0; pr < 2; pr++)
                ldsm4(bq4[pr], bLd + so + (uint32_t)(pr * (16 * 144) + ks * 32));
#pragma unroll
            for (int mt = 0; mt < 4; mt++) {
#pragma unroll
                for (int nt = 0; nt < 4; nt++) {
                    uint32_t bb[2];
                    bb[0] = bq4[nt >> 1][nt & 1];
                    bb[1] = bq4[nt >> 1][2 + (nt & 1)];
                    mma_f16(acc[mt][nt], af[mt], bb);
                }
            }
        }
        __syncthreads();
        if (kt + 2 < nk) {
            uint32_t so2 = (uint32_t)((kt & 1) * STAGE_BYTES);
            const int koff = (kt + 2) * 64;
#pragma unroll
            for (int j = 0; j < 4; j++) {
                cp_async16(dA[j] + so2, srcA[j] + koff);
                cp_async16(dW[j] + so2, srcW[j] + koff);
            }
        }
        cp_commit();
    }

#pragma unroll
    for (int mt = 0; mt < 4; mt++) {
#pragma unroll
        for (int nt = 0; nt < 4; nt++) {
            int row = bm + warp_m * 64 + mt * 16 + g;
            int col = bn + warp_n * 32 + nt * 8 + 2 * t;
#pragma unroll
            for (int half_i = 0; half_i < 2; half_i++) {
                int r = row + half_i * 8;
                float v0 = acc[mt][nt][half_i * 2 + 0] + bias[col];
                float v1 = acc[mt][nt][half_i * 2 + 1] + bias[col + 1];
                if (EPI == 0) {
                    *(__half2*)((__half*)Cv + (size_t)r * N + col) = __floats2half2_rn(v0, v1);
                } else if (EPI == 1) {
                    float z0 = 0.7978845608028654f * (v0 + 0.044715f * v0 * v0 * v0);
                    float z1 = 0.7978845608028654f * (v1 + 0.044715f * v1 * v1 * v1);
                    v0 = v0 / (1.f + __expf(-2.f * z0));
                    v1 = v1 / (1.f + __expf(-2.f * z1));
                    *(__half2*)((__half*)Cv + (size_t)r * N + col) = __floats2half2_rn(v0, v1);
                } else {
                    v0 += res[(size_t)r * N + col];
                    v1 += res[(size_t)r * N + col + 1];
                    float2 o; o.x = v0; o.y = v1;
                    *(float2*)((float*)Cv + (size_t)r * N + col) = o;
                }
            }
        }
    }
}

// ================= fp16 mma flash attention (R13/R14-proven) ==============
#define AKSTR 72
#define ATT_SH (2 * 64 * AKSTR)
#define ATT_SMEM (2 * ATT_SH * 2)

__global__ void __launch_bounds__(256, 2)
attn_mma(const __half* __restrict__ q, const __half* __restrict__ k,
         const __half* __restrict__ v, __half* __restrict__ out) {
    extern __shared__ __half sm[];
    const uint32_t smb = smem_u32(sm);
    const int tid = threadIdx.x, wid = tid >> 5, lane = tid & 31;
    const int g = lane >> 2, t = lane & 3;
    const int bh = blockIdx.x, b = bh >> 4, h = bh & 15;
    const int q0 = blockIdx.y * 128 + wid * 16;

    const int sr = tid >> 2;
    const int sseg = (tid & 3) * 8;
    const __half* kb0 = k + ((size_t)b * Sq) * Dq + h * HDq;
    const __half* vb0 = v + ((size_t)b * Sq) * Dq + h * HDq;
    const uint32_t dK = smb + (uint32_t)((sr * AKSTR + sseg) * 2);
    const uint32_t dV = dK + (uint32_t)(64 * AKSTR * 2);

    uint32_t aq[4][4];
    {
        const __half* qb = q + ((size_t)(b * Sq + q0)) * Dq + h * HDq;
        const __half2 sc = __floats2half2_rn(0.125f, 0.125f);
#pragma unroll
        for (int ks = 0; ks < 4; ks++) {
            __half2 x0 = __hmul2(*(const __half2*)(qb + (size_t)g * Dq + ks * 16 + 2 * t), sc);
            __half2 x1 = __hmul2(*(const __half2*)(qb + (size_t)(g + 8) * Dq + ks * 16 + 2 * t), sc);
            __half2 x2 = __hmul2(*(const __half2*)(qb + (size_t)g * Dq + ks * 16 + 2 * t + 8), sc);
            __half2 x3 = __hmul2(*(const __half2*)(qb + (size_t)(g + 8) * Dq + ks * 16 + 2 * t + 8), sc);
            aq[ks][0] = *(uint32_t*)&x0;
            aq[ks][1] = *(uint32_t*)&x1;
            aq[ks][2] = *(uint32_t*)&x2;
            aq[ks][3] = *(uint32_t*)&x3;
        }
    }
    const uint32_t kLd = smb + (uint32_t)((((lane & 15)) * AKSTR + 8 * (lane >> 4)) * 2);
    const uint32_t vLd = kLd + (uint32_t)(64 * AKSTR * 2);

    float o[8][4];
#pragma unroll
    for (int nt = 0; nt < 8; nt++)
#pragma unroll
        for (int u = 0; u < 4; u++) o[nt][u] = 0.f;
    float m0 = -1e30f, m1 = -1e30f, l0 = 0.f, l1 = 0.f;

    const int NT = Sq / 64;
    cp_async16(dK,       kb0 + (size_t)sr * Dq + sseg);
    cp_async16(dK + 64u, kb0 + (size_t)sr * Dq + sseg + 32);
    cp_async16(dV,       vb0 + (size_t)sr * Dq + sseg);
    cp_async16(dV + 64u, vb0 + (size_t)sr * Dq + sseg + 32);
    cp_commit();

    for (int kt = 0; kt < NT; kt++) {
        cp_wait<0>();
        __syncthreads();
        if (kt + 1 < NT) {
            uint32_t so = (uint32_t)(((kt + 1) & 1) * ATT_SH * 2);
            const __half* kb = kb0 + (size_t)(kt + 1) * 64 * Dq;
            const __half* vb = vb0 + (size_t)(kt + 1) * 64 * Dq;
            cp_async16(dK + so,       kb + (size_t)sr * Dq + sseg);
            cp_async16(dK + so + 64u, kb + (size_t)sr * Dq + sseg + 32);
            cp_async16(dV + so,       vb + (size_t)sr * Dq + sseg);
            cp_async16(dV + so + 64u, vb + (size_t)sr * Dq + sseg + 32);
            cp_commit();
        }
        const uint32_t so = (uint32_t)((kt & 1) * ATT_SH * 2);

#pragma unroll
        for (int sub = 0; sub < 2; sub++) {
            float s[4][4];
#pragma unroll
            for (int nt = 0; nt < 4; nt++)
#pragma unroll
                for (int u = 0; u < 4; u++) s[nt][u] = 0.f;
#pragma unroll
            for (int ks = 0; ks < 4; ks++) {
#pragma unroll
                for (int pr = 0; pr < 2; pr++) {
                    uint32_t kq[4];
                    ldsm4(kq, kLd + so + (uint32_t)((((sub * 32 + pr * 16) * AKSTR) + ks * 16) * 2));
#pragma unroll
                    for (int half_n = 0; half_n < 2; half_n++) {
                        uint32_t bb[2];
                        bb[0] = kq[half_n];
                        bb[1] = kq[2 + half_n];
                        mma_f16(s[pr * 2 + half_n], aq[ks], bb);
                    }
                }
            }
            float mx0 = fmaxf(fmaxf(s[0][0], s[0][1]), fmaxf(s[1][0], s[1][1]));
            mx0 = fmaxf(mx0, fmaxf(fmaxf(s[2][0], s[2][1]), fmaxf(s[3][0], s[3][1])));
            float mx1 = fmaxf(fmaxf(s[0][2], s[0][3]), fmaxf(s[1][2], s[1][3]));
            mx1 = fmaxf(mx1, fmaxf(fmaxf(s[2][2], s[2][3]), fmaxf(s[3][2], s[3][3])));
            mx0 = fmaxf(mx0, __shfl_xor_sync(0xffffffffu, mx0, 1));
            mx0 = fmaxf(mx0, __shfl_xor_sync(0xffffffffu, mx0, 2));
            mx1 = fmaxf(mx1, __shfl_xor_sync(0xffffffffu, mx1, 1));
            mx1 = fmaxf(mx1, __shfl_xor_sync(0xffffffffu, mx1, 2));
            float nm0 = fmaxf(m0, mx0), nm1 = fmaxf(m1, mx1);
            float c0 = __expf(m0 - nm0), c1 = __expf(m1 - nm1);
            float sum0 = 0.f, sum1 = 0.f;
#pragma unroll
            for (int nt = 0; nt < 4; nt++) {
                s[nt][0] = __expf(s[nt][0] - nm0);
                s[nt][1] = __expf(s[nt][1] - nm0);
                s[nt][2] = __expf(s[nt][2] - nm1);
                s[nt][3] = __expf(s[nt][3] - nm1);
                sum0 += s[nt][0] + s[nt][1];
                sum1 += s[nt][2] + s[nt][3];
            }
            sum0 += __shfl_xor_sync(0xffffffffu, sum0, 1);
            sum0 += __shfl_xor_sync(0xffffffffu, sum0, 2);
            sum1 += __shfl_xor_sync(0xffffffffu, sum1, 1);
            sum1 += __shfl_xor_sync(0xffffffffu, sum1, 2);
            l0 = l0 * c0 + sum0;
            l1 = l1 * c1 + sum1;
#pragma unroll
            for (int nt = 0; nt < 8; nt++) {
                o[nt][0] *= c0; o[nt][1] *= c0;
                o[nt][2] *= c1; o[nt][3] *= c1;
            }
            m0 = nm0; m1 = nm1;

            uint32_t ap[2][4];
#pragma unroll
            for (int j = 0; j < 2; j++) {
                __half2 p0 = __floats2half2_rn(s[2 * j][0], s[2 * j][1]);
                __half2 p1 = __floats2half2_rn(s[2 * j][2], s[2 * j][3]);
                __half2 p2 = __floats2half2_rn(s[2 * j + 1][0], s[2 * j + 1][1]);
                __half2 p3 = __floats2half2_rn(s[2 * j + 1][2], s[2 * j + 1][3]);
                ap[j][0] = *(uint32_t*)&p0;
                ap[j][1] = *(uint32_t*)&p1;
                ap[j][2] = *(uint32_t*)&p2;
                ap[j][3] = *(uint32_t*)&p3;
            }
#pragma unroll
            for (int j = 0; j < 2; j++) {
#pragma unroll
                for (int np = 0; np < 4; np++) {
                    uint32_t vq[4];
                    ldsm4t(vq, vLd + so + (uint32_t)((((sub * 32 + j * 16) * AKSTR) + np * 16) * 2));
#pragma unroll
                    for (int half_n = 0; half_n < 2; half_n++) {
                        uint32_t bb[2];
                        bb[0] = vq[half_n * 2];
                        bb[1] = vq[half_n * 2 + 1];
                        mma_f16(o[np * 2 + half_n], ap[j], bb);
                    }
                }
            }
        }
        __syncthreads();
    }

    float i0 = 1.f / l0, i1 = 1.f / l1;
    __half* ob = out + ((size_t)(b * Sq + q0)) * Dq + h * HDq;
#pragma unroll
    for (int nt = 0; nt < 8; nt++) {
        *(__half2*)(ob + (size_t)g * Dq + nt * 8 + 2 * t) =
            __floats2half2_rn(o[nt][0] * i0, o[nt][1] * i0);
        *(__half2*)(ob + (size_t)(g + 8) * Dq + nt * 8 + 2 * t) =
            __floats2half2_rn(o[nt][2] * i1, o[nt][3] * i1);
    }
}

// ================= launch =================
extern "C" void kernel_launch(void* const* d_in, const int* in_sizes, int n_in,
                              void* d_out, int out_size) {
    const float* x     = (const float*)d_in[0];
    const float* Wq    = (const float*)d_in[1];
    const float* bq    = (const float*)d_in[2];
    const float* Wk    = (const float*)d_in[3];
    const float* bk    = (const float*)d_in[4];
    const float* Wv    = (const float*)d_in[5];
    const float* bv    = (const float*)d_in[6];
    const float* Wo    = (const float*)d_in[7];
    const float* bo    = (const float*)d_in[8];
    const float* ln1_g = (const float*)d_in[9];
    const float* ln1_b = (const float*)d_in[10];
    const float* W1    = (const float*)d_in[11];
    const float* b1    = (const float*)d_in[12];
    const float* W2    = (const float*)d_in[13];
    const float* b2    = (const float*)d_in[14];
    const float* ln2_g = (const float*)d_in[15];
    const float* ln2_b = (const float*)d_in[16];
    float* out = (float*)d_out;

    __half *h, *q, *k, *v, *att, *h2, *mlp, *wq, *wk, *wv, *wo, *w1, *w2;
    float *x2;
    cudaGetSymbolAddress((void**)&h,   g_h);
    cudaGetSymbolAddress((void**)&q,   g_q);
    cudaGetSymbolAddress((void**)&k,   g_k);
    cudaGetSymbolAddress((void**)&v,   g_v);
    cudaGetSymbolAddress((void**)&att, g_att);
    cudaGetSymbolAddress((void**)&x2,  g_x2);
    cudaGetSymbolAddress((void**)&h2,  g_h2);
    cudaGetSymbolAddress((void**)&mlp, g_mlp);
    cudaGetSymbolAddress((void**)&wq,  g_wq);
    cudaGetSymbolAddress((void**)&wk,  g_wk);
    cudaGetSymbolAddress((void**)&wv,  g_wv);
    cudaGetSymbolAddress((void**)&wo,  g_wo);
    cudaGetSymbolAddress((void**)&w1,  g_w1);
    cudaGetSymbolAddress((void**)&w2,  g_w2);

    cudaFuncSetAttribute(gemm_mma<0>, cudaFuncAttributeMaxDynamicSharedMemorySize, GEMM_SMEM);
    cudaFuncSetAttribute(gemm_mma<1>, cudaFuncAttributeMaxDynamicSharedMemorySize, GEMM_SMEM);
    cudaFuncSetAttribute(gemm_mma<2>, cudaFuncAttributeMaxDynamicSharedMemorySize, GEMM_SMEM);
    cudaFuncSetAttribute(attn_mma, cudaFuncAttributeMaxDynamicSharedMemorySize, ATT_SMEM);

    // 0) convert weights to fp16
    const int WTOT4 = (4 * Dq * Dq + 2 * Fq * Dq) / 4;
    wcvt_kernel<<<WTOT4 / 256, 256>>>(Wq, Wk, Wv, Wo, W1, W2, wq, wk, wv, wo, w1, w2);

    // 1) LN1 -> h (half), warp-per-row
    ln_kernel<<<NTOK / 8, 256>>>(x, ln1_g, ln1_b, h);

    // 2) QKV -> half (3 separate launches, R14-proven)
    dim3 gqkv(Dq / 128, NTOK / 128);
    gemm_mma<0><<<gqkv, 256, GEMM_SMEM>>>(h, wq, bq, nullptr, q, NTOK, Dq, Dq);
    gemm_mma<0><<<gqkv, 256, GEMM_SMEM>>>(h, wk, bk, nullptr, k, NTOK, Dq, Dq);
    gemm_mma<0><<<gqkv, 256, GEMM_SMEM>>>(h, wv, bv, nullptr, v, NTOK, Dq, Dq);

    // 3) attention (fp16 mma) -> att (half)
    dim3 gattn(Bq * Hq, Sq / 128);
    attn_mma<<<gattn, 256, ATT_SMEM>>>(q, k, v, att);

    // 4) output projection + residual -> x2
    dim3 go(Dq / 128, NTOK / 128);
    gemm_mma<2><<<go, 256, GEMM_SMEM>>>(att, wo, bo, x, x2, NTOK, Dq, Dq);

    // 5) LN2 -> h2 (half)
    ln_kernel<<<NTOK / 8, 256>>>(x2, ln2_g, ln2_b, h2);

    // 6) MLP up + gelu -> mlp (half)
    dim3 g1(Fq / 128, NTOK / 128);
    gemm_mma<1><<<g1, 256, GEMM_SMEM>>>(h2, w1, b1, nullptr, mlp, NTOK, Fq, Dq);

    // 7) MLP down + residual -> out
    dim3 g2(Dq / 128, NTOK / 128);
    gemm_mma<2><<<g2, 256, GEMM_SMEM>>>(mlp, w2, b2, x2, out, NTOK, Dq, Fq);
}